// round 7
// baseline (speedup 1.0000x reference)
#include <cuda_runtime.h>
#include <cuda_bf16.h>
#include <math.h>
#include <stdint.h>

// LSTM: B=64, T=512, I=H=1024. Output: h_T [64,1024] then c_T [64,1024] (fp32).
#define Bsz  64
#define Tlen 512
#define Idim 1024
#define Hdim 1024
#define G4   4096   // 4*H
#define KP   3072   // 3*1024: hi/lo-split K dimension

// ---------------- scratch (device globals: no allocation allowed) ----------------
// g_xg layout: [cta 128][t 512][row 64][32 cols(gate*8+unit)]  (gates f,i,g,o)
__device__ __align__(16) float         g_xg[(size_t)Tlen * Bsz * G4];
__device__ __align__(16) __nv_bfloat16 g_xbf[(size_t)Tlen * Bsz * KP]; // [m][3072] A'=[x_hi|x_lo|x_hi]
__device__ __align__(16) __nv_bfloat16 g_Wbp[(size_t)G4 * KP];          // [n][3072] B'=[W_hi|W_hi|W_lo]
__device__ __align__(16) float         g_bsum[G4];                      // fused biases
// h' double-buffered in MMA A-FRAGMENT layout:
// [buf 2][kt 128 (0-63 hi, 64-127 lo)][mt 4][lane 32][reg 4] uint32
__device__ __align__(16) uint32_t      g_hF[2 * 128 * 4 * 32 * 4];
__device__ unsigned g_bar_cnt;
__device__ unsigned g_bar_gen;

// ---------------- helpers ----------------
__device__ __forceinline__ uint32_t smem_to_u32(const void* p) {
    uint32_t a;
    asm("{ .reg .u64 t; cvta.to.shared.u64 t, %1; cvt.u32.u64 %0, t; }" : "=r"(a) : "l"(p));
    return a;
}
__device__ __forceinline__ void ldsm_x4(uint32_t& r0, uint32_t& r1, uint32_t& r2, uint32_t& r3,
                                        uint32_t addr) {
    asm volatile("ldmatrix.sync.aligned.m8n8.x4.shared.b16 {%0,%1,%2,%3}, [%4];"
                 : "=r"(r0), "=r"(r1), "=r"(r2), "=r"(r3) : "r"(addr));
}
__device__ __forceinline__ void mma16816(float* c, const uint32_t* a, uint32_t b0, uint32_t b1) {
    asm volatile(
        "mma.sync.aligned.m16n8k16.row.col.f32.bf16.bf16.f32 "
        "{%0,%1,%2,%3}, {%4,%5,%6,%7}, {%8,%9}, {%0,%1,%2,%3};"
        : "+f"(c[0]), "+f"(c[1]), "+f"(c[2]), "+f"(c[3])
        : "r"(a[0]), "r"(a[1]), "r"(a[2]), "r"(a[3]), "r"(b0), "r"(b1));
}
__device__ __forceinline__ float sigf(float x) { return 1.f / (1.f + __expf(-x)); }

// ---------------- pack W into bf16 hi/lo [n][3072] + fused biases ----------------
__global__ void packW_kernel(const float* __restrict__ Wif, const float* __restrict__ Wii,
                             const float* __restrict__ Wig, const float* __restrict__ Wio,
                             const float* __restrict__ bif_, const float* __restrict__ bhf,
                             const float* __restrict__ bii_, const float* __restrict__ bhi,
                             const float* __restrict__ big_, const float* __restrict__ bhg,
                             const float* __restrict__ bio_, const float* __restrict__ bho)
{
    size_t idx = (size_t)blockIdx.x * blockDim.x + threadIdx.x;
    if (idx < (size_t)G4 * KP) {
        int n = (int)(idx / KP), c = (int)(idx % KP);
        int sec = c >> 10, k = c & 1023;
        int gate = n >> 10, hid = n & 1023;
        const float* W = (gate == 0) ? Wif : (gate == 1) ? Wii : (gate == 2) ? Wig : Wio;
        float v = W[k * Hdim + hid];
        __nv_bfloat16 hi = __float2bfloat16(v);
        g_Wbp[idx] = (sec == 2) ? __float2bfloat16(v - __bfloat162float(hi)) : hi;
    }
    if (idx < G4) {
        int gate = (int)(idx >> 10), hid = (int)(idx & 1023);
        const float* bx = (gate == 0) ? bif_ : (gate == 1) ? bii_ : (gate == 2) ? big_ : bio_;
        const float* bh = (gate == 0) ? bhf  : (gate == 1) ? bhi  : (gate == 2) ? bhg  : bho;
        g_bsum[idx] = bx[hid] + bh[hid];
    }
}

// ---------------- x -> bf16 hi/lo [m][3072] ----------------
__global__ void xconv_kernel(const float* __restrict__ x)
{
    size_t idx = (size_t)blockIdx.x * blockDim.x + threadIdx.x;
    if (idx >= (size_t)Tlen * Bsz * KP) return;
    int m = (int)(idx / KP), c = (int)(idx % KP);
    int sec = c >> 10, k = c & 1023;
    int b = m & 63, t = m >> 6;
    float v = x[((size_t)(b * Tlen + t)) * Idim + k];
    __nv_bfloat16 hi = __float2bfloat16(v);
    g_xbf[idx] = (sec == 1) ? __float2bfloat16(v - __bfloat162float(hi)) : hi;
}

// ---------------- HMMA input-projection GEMM (writes rec-friendly xg layout) ----------------
#define PBK   32
#define PNCH  (KP / PBK)   // 96
#define SROW  40           // bf16 elems per smem row (80 B)

__global__ __launch_bounds__(256) void proj_mma_kernel()
{
    __shared__ __align__(16) __nv_bfloat16 sA[2][128 * SROW];
    __shared__ __align__(16) __nv_bfloat16 sB[2][128 * SROW];

    const int tid = threadIdx.x, lane = tid & 31, wid = tid >> 5;
    const int bn0 = blockIdx.x * 128, bm0 = blockIdx.y * 128;
    const int wm = wid >> 2, wn = wid & 3;          // warp grid 2x4

    const uint32_t sAb = smem_to_u32(sA);
    const uint32_t sBb = smem_to_u32(sB);
    const int rowoff = ((lane >> 3) & 1) * 8 + (lane & 7);
    const int kkoff  = (lane >> 4) * 8;

    float acc[4][4][4];
#pragma unroll
    for (int i = 0; i < 4; ++i)
#pragma unroll
        for (int j = 0; j < 4; ++j)
#pragma unroll
            for (int r = 0; r < 4; ++r) acc[i][j][r] = 0.f;

#pragma unroll
    for (int q = 0; q < 2; ++q) {
        int idx = tid + q * 256;
        int row = idx >> 2, j = idx & 3;
        *(uint4*)((char*)sA[0] + row * 80 + j * 16) =
            *(const uint4*)(g_xbf + (size_t)(bm0 + row) * KP + j * 8);
        *(uint4*)((char*)sB[0] + row * 80 + j * 16) =
            *(const uint4*)(g_Wbp + (size_t)(bn0 + row) * KP + j * 8);
    }
    __syncthreads();

    int buf = 0;
    for (int ch = 0; ch < PNCH; ++ch) {
        uint4 pa[2], pb[2];
        const bool has_next = (ch + 1 < PNCH);
        if (has_next) {
            const int kb = (ch + 1) * PBK;
#pragma unroll
            for (int q = 0; q < 2; ++q) {
                int idx = tid + q * 256;
                int row = idx >> 2, j = idx & 3;
                pa[q] = *(const uint4*)(g_xbf + (size_t)(bm0 + row) * KP + kb + j * 8);
                pb[q] = *(const uint4*)(g_Wbp + (size_t)(bn0 + row) * KP + kb + j * 8);
            }
        }
        const uint32_t aBase = sAb + buf * (128 * SROW * 2);
        const uint32_t bBase = sBb + buf * (128 * SROW * 2);
#pragma unroll
        for (int k0 = 0; k0 < PBK; k0 += 16) {
            uint32_t af[4][4], bfr[2][4];
#pragma unroll
            for (int mt = 0; mt < 4; ++mt) {
                uint32_t addr = aBase +
                    (uint32_t)(((wm * 64 + mt * 16 + rowoff) * SROW + k0 + kkoff) * 2);
                ldsm_x4(af[mt][0], af[mt][1], af[mt][2], af[mt][3], addr);
            }
#pragma unroll
            for (int pt = 0; pt < 2; ++pt) {
                uint32_t addr = bBase +
                    (uint32_t)(((wn * 32 + pt * 16 + rowoff) * SROW + k0 + kkoff) * 2);
                ldsm_x4(bfr[pt][0], bfr[pt][1], bfr[pt][2], bfr[pt][3], addr);
            }
#pragma unroll
            for (int mt = 0; mt < 4; ++mt)
#pragma unroll
                for (int nt = 0; nt < 4; ++nt) {
                    int pt = nt >> 1, hi = nt & 1;
                    mma16816(acc[mt][nt], af[mt], bfr[pt][hi], bfr[pt][hi + 2]);
                }
        }
        if (has_next) {
#pragma unroll
            for (int q = 0; q < 2; ++q) {
                int idx = tid + q * 256;
                int row = idx >> 2, j = idx & 3;
                *(uint4*)((char*)sA[buf ^ 1] + row * 80 + j * 16) = pa[q];
                *(uint4*)((char*)sB[buf ^ 1] + row * 80 + j * 16) = pb[q];
            }
        }
        __syncthreads();
        buf ^= 1;
    }

    // epilogue -> xg layout [cta][t][row][gate*8+unit], bias folded in
    const int erow = lane >> 2, ecol = (lane & 3) * 2;
#pragma unroll
    for (int mt = 0; mt < 4; ++mt)
#pragma unroll
        for (int nt = 0; nt < 4; ++nt) {
            int r = bm0 + wm * 64 + mt * 16 + erow;           // m = t*64 + b
            int c = bn0 + wn * 32 + nt * 8 + ecol;
            int tt = r >> 6, b = r & 63;
            int gate = c >> 10, cc = c & 1023, ctaId = cc >> 3, unit = cc & 7;
            size_t base = (size_t)ctaId * (512 * 64 * 32) + (size_t)tt * 2048 + b * 32 + gate * 8 + unit;
            float b0 = g_bsum[c], b1 = g_bsum[c + 1];
            float2 o0 = {acc[mt][nt][0] + b0, acc[mt][nt][1] + b1};
            float2 o1 = {acc[mt][nt][2] + b0, acc[mt][nt][3] + b1};
            *(float2*)(g_xg + base) = o0;            // row b
            *(float2*)(g_xg + base + 8 * 32) = o1;   // row b+8
        }
}

// ---------------- grid barrier ----------------
__device__ __forceinline__ void grid_sync(unsigned nb)
{
    __threadfence();
    __syncthreads();
    if (threadIdx.x == 0) {
        unsigned gen = *(volatile unsigned*)&g_bar_gen;
        unsigned arr = atomicAdd(&g_bar_cnt, 1);
        if (arr == nb - 1) {
            g_bar_cnt = 0;
            __threadfence();
            *(volatile unsigned*)&g_bar_gen = gen + 1;
        } else {
            while (*(volatile unsigned*)&g_bar_gen == gen) { __nanosleep(32); }
        }
    }
    __syncthreads();
}

// ---------------- HMMA persistent recurrence, fragment-layout h ----------------
// 128 CTAs; CTA owns 8 units x 4 gates = 32 Wh' columns resident in smem.
// h' stored in A-fragment order: one dense LDG.128 per (ktile, mtile) per warp.
// Warps: mt = wid&3 (16-row tile), kh = wid>>2 (K-half, 96 ktiles each).
#define BPITCH 3080
__global__ __launch_bounds__(256) void lstm_rec_mma(
    const float* __restrict__ Whf, const float* __restrict__ Whi,
    const float* __restrict__ Whg, const float* __restrict__ Who,
    float* __restrict__ out)
{
    extern __shared__ __align__(16) char sm[];
    __nv_bfloat16* Bs = (__nv_bfloat16*)sm;          // 32 * 3080 * 2B = 197120
    float* red = (float*)(sm + 32 * BPITCH * 2);     // 4*16*32 fp32 = 8192

    const int tid = threadIdx.x, lane = tid & 31, wid = tid >> 5;
    const int cta = blockIdx.x;
    const int mt = wid & 3, kh = wid >> 2;
    const unsigned NB = gridDim.x;

    // fill Wh' slice: sec0,1 = hi, sec2 = lo
    for (int idx = tid; idx < 32 * 1024; idx += 256) {
        int c = idx >> 10, k = idx & 1023;
        int g = c >> 3, u = c & 7;
        const float* W = (g == 0) ? Whf : (g == 1) ? Whi : (g == 2) ? Whg : Who;
        float v = W[k * Hdim + cta * 8 + u];
        __nv_bfloat16 hi = __float2bfloat16(v);
        __nv_bfloat16 lo = __float2bfloat16(v - __bfloat162float(hi));
        Bs[c * BPITCH + k] = hi;
        Bs[c * BPITCH + 1024 + k] = hi;
        Bs[c * BPITCH + 2048 + k] = lo;
    }
    // zero h fragment buf0 (grid-wide cooperative)
    for (int idx = cta * 256 + tid; idx < 128 * 4 * 32 * 4; idx += 128 * 256)
        g_hF[idx] = 0u;
    grid_sync(NB);

    const uint32_t Bbase = smem_to_u32(Bs);
    const int rowoff = ((lane >> 3) & 1) * 8 + (lane & 7);
    const int kkoff  = (lane >> 4) * 8;
    const int erow   = lane >> 2;
    const int arow   = mt * 16 + erow;
    const int uu     = (lane & 3) * 2;
    const size_t ctaSlab = (size_t)cta * (512 * 64 * 32);

    float cf[4] = {0.f, 0.f, 0.f, 0.f};  // c state (kh==0): [row-half][unit]

    for (int t = 0; t < Tlen; ++t) {
        const uint32_t* __restrict__ hF = g_hF + (size_t)(t & 1) * (128 * 4 * 32 * 4);

        // prefetch this step's xg slab (kh==0 warps) to hide DRAM latency behind MMAs
        float2 xv[4][2];
        if (kh == 0) {
#pragma unroll
            for (int nt = 0; nt < 4; ++nt) {
                const float* xg0 = g_xg + ctaSlab + (size_t)t * 2048 + arow * 32 + nt * 8 + uu;
                xv[nt][0] = *(const float2*)xg0;
                xv[nt][1] = *(const float2*)(xg0 + 8 * 32);
            }
        }

        float acc[4][4];
#pragma unroll
        for (int i = 0; i < 4; ++i)
#pragma unroll
            for (int j = 0; j < 4; ++j) acc[i][j] = 0.f;

        const int ktb = kh * 96;
#pragma unroll 4
        for (int s = 0; s < 96; ++s) {
            const int ktl = ktb + s;                        // logical ktile 0..191
            const int kt  = (ktl < 128) ? ktl : ktl - 128;  // physical (hi reused)
            uint4 av4 = *(const uint4*)(hF + ((kt * 4 + mt) * 32 + lane) * 4);
            uint32_t av[4] = {av4.x, av4.y, av4.z, av4.w};
            const int kp = ktl * 16;                        // B' k-offset 0..3071
#pragma unroll
            for (int pt = 0; pt < 2; ++pt) {
                uint32_t bb[4];
                uint32_t addr = Bbase +
                    (uint32_t)(((pt * 16 + rowoff) * BPITCH + kp + kkoff) * 2);
                ldsm_x4(bb[0], bb[1], bb[2], bb[3], addr);
                mma16816(acc[pt * 2 + 0], av, bb[0], bb[2]);
                mma16816(acc[pt * 2 + 1], av, bb[1], bb[3]);
            }
        }

        if (kh == 1) {
#pragma unroll
            for (int nt = 0; nt < 4; ++nt) {
                int base = mt * 512 + erow * 32 + nt * 8 + uu;
                *(float2*)&red[base]       = make_float2(acc[nt][0], acc[nt][1]);
                *(float2*)&red[base + 256] = make_float2(acc[nt][2], acc[nt][3]);
            }
        }
        __syncthreads();
        if (kh == 0) {
            float p[4][4];
#pragma unroll
            for (int nt = 0; nt < 4; ++nt) {
                int base = mt * 512 + erow * 32 + nt * 8 + uu;
                float2 r1 = *(float2*)&red[base];
                float2 r2 = *(float2*)&red[base + 256];
                p[nt][0] = acc[nt][0] + r1.x + xv[nt][0].x;
                p[nt][1] = acc[nt][1] + r1.y + xv[nt][0].y;
                p[nt][2] = acc[nt][2] + r2.x + xv[nt][1].x;
                p[nt][3] = acc[nt][3] + r2.y + xv[nt][1].y;
            }
            uint32_t* hw = g_hF + (size_t)((t + 1) & 1) * (128 * 4 * 32 * 4);
            const int ktHi = cta >> 1, ktLo = 64 + (cta >> 1);
            const int lt   = erow * 4 + (uu >> 1);
            const int rpar = 2 * (cta & 1);
#pragma unroll
            for (int j = 0; j < 2; ++j) {          // row-half: arow, arow+8
                float hn[2];
#pragma unroll
                for (int q = 0; q < 2; ++q) {      // unit: uu, uu+1
                    float f  = sigf(p[0][j * 2 + q]);
                    float ii = sigf(p[1][j * 2 + q]);
                    float gg = tanhf(p[2][j * 2 + q]);
                    float oo = sigf(p[3][j * 2 + q]);
                    float cn = f * cf[j * 2 + q] + ii * gg;
                    cf[j * 2 + q] = cn;
                    hn[q] = tanhf(cn) * oo;
                }
                __nv_bfloat16 h0 = __float2bfloat16(hn[0]);
                __nv_bfloat16 h1 = __float2bfloat16(hn[1]);
                __nv_bfloat16 l0 = __float2bfloat16(hn[0] - __bfloat162float(h0));
                __nv_bfloat16 l1 = __float2bfloat16(hn[1] - __bfloat162float(h1));
                uint32_t hp = (uint32_t)__bfloat16_as_ushort(h0) |
                              ((uint32_t)__bfloat16_as_ushort(h1) << 16);
                uint32_t lp = (uint32_t)__bfloat16_as_ushort(l0) |
                              ((uint32_t)__bfloat16_as_ushort(l1) << 16);
                // fragment slots: reg = j + 2*(cta&1)
                hw[(ktHi * 4 + mt) * 128 + lt * 4 + j + rpar] = hp;
                hw[(ktLo * 4 + mt) * 128 + lt * 4 + j + rpar] = lp;
                if (t == Tlen - 1) {
                    int row = arow + j * 8;
                    *(float2*)(out + row * 1024 + cta * 8 + uu) = make_float2(hn[0], hn[1]);
                    *(float2*)(out + 65536 + row * 1024 + cta * 8 + uu) =
                        make_float2(cf[j * 2 + 0], cf[j * 2 + 1]);
                }
            }
        }
        grid_sync(NB);
    }
}

// ---------------- launch ----------------
extern "C" void kernel_launch(void* const* d_in, const int* in_sizes, int n_in,
                              void* d_out, int out_size)
{
    // metadata order = setup_inputs() dict order:
    // 0:x, 1:W_ii, 2:W_hi, 3:W_if, 4:W_hf, 5:W_ig, 6:W_hg, 7:W_io, 8:W_ho,
    // 9:b_ii, 10:b_hi, 11:b_if, 12:b_hf, 13:b_ig, 14:b_hg, 15:b_io, 16:b_ho
    const float* x   = (const float*)d_in[0];
    const float* Wii = (const float*)d_in[1];
    const float* Whi = (const float*)d_in[2];
    const float* Wif = (const float*)d_in[3];
    const float* Whf = (const float*)d_in[4];
    const float* Wig = (const float*)d_in[5];
    const float* Whg = (const float*)d_in[6];
    const float* Wio = (const float*)d_in[7];
    const float* Who = (const float*)d_in[8];
    const float* bii = (const float*)d_in[9];
    const float* bhi = (const float*)d_in[10];
    const float* bif = (const float*)d_in[11];
    const float* bhf = (const float*)d_in[12];
    const float* big = (const float*)d_in[13];
    const float* bhg = (const float*)d_in[14];
    const float* bio = (const float*)d_in[15];
    const float* bho = (const float*)d_in[16];
    float* out = (float*)d_out;

    // 1. pack W (bf16 hi/lo) + fused biases
    {
        size_t tot = (size_t)G4 * KP;
        packW_kernel<<<(unsigned)((tot + 255) / 256), 256>>>(Wif, Wii, Wig, Wio,
                                                             bif, bhf, bii, bhi,
                                                             big, bhg, bio, bho);
    }
    // 2. x -> bf16 hi/lo
    {
        size_t tot = (size_t)Tlen * Bsz * KP;
        xconv_kernel<<<(unsigned)((tot + 255) / 256), 256>>>(x);
    }
    // 3. HMMA input projection
    proj_mma_kernel<<<dim3(G4 / 128, (Tlen * Bsz) / 128), 256>>>();

    // 4. HMMA persistent recurrence (fragment-layout h)
    {
        int smem_bytes = 32 * BPITCH * 2 + 4 * 16 * 32 * 4;  // 197120 + 8192 = 205312
        cudaFuncSetAttribute(lstm_rec_mma, cudaFuncAttributeMaxDynamicSharedMemorySize, smem_bytes);
        lstm_rec_mma<<<128, 256, smem_bytes>>>(Whf, Whi, Whg, Who, out);
    }
}

// round 8
// speedup vs baseline: 1.9180x; 1.9180x over previous
#include <cuda_runtime.h>
#include <cuda_bf16.h>
#include <math.h>
#include <stdint.h>

// LSTM: B=64, T=512, I=H=1024. Output: h_T [64,1024] then c_T [64,1024] (fp32).
#define Bsz  64
#define Tlen 512
#define Idim 1024
#define Hdim 1024
#define G4   4096
#define KP   3072   // 3*1024 hi/lo-split K

// ---------------- scratch ----------------
// g_xg: [cta 256][t 512][row 64][16 cols(unit*4+gate)], gates f,i,g,o
__device__ __align__(16) float         g_xg[(size_t)Tlen * Bsz * G4];
__device__ __align__(16) __nv_bfloat16 g_xbf[(size_t)Tlen * Bsz * KP]; // [m][3072] A'=[x_hi|x_lo|x_hi]
__device__ __align__(16) __nv_bfloat16 g_Wbp[(size_t)G4 * KP];          // [n][3072] B'=[W_hi|W_hi|W_lo]
__device__ __align__(16) float         g_bsum[G4];
// h' double buf, MMA A-fragment layout: [buf 2][kt 128 (0-63 hi,64-127 lo)][mt 4][lane 32][reg 4] u32
__device__ __align__(16) uint32_t      g_hF[2 * 128 * 4 * 32 * 4];
__device__ unsigned g_bar_cnt;
__device__ unsigned g_bar_gen;

// ---------------- helpers ----------------
__device__ __forceinline__ uint32_t smem_to_u32(const void* p) {
    uint32_t a;
    asm("{ .reg .u64 t; cvta.to.shared.u64 t, %1; cvt.u32.u64 %0, t; }" : "=r"(a) : "l"(p));
    return a;
}
__device__ __forceinline__ void ldsm_x4(uint32_t& r0, uint32_t& r1, uint32_t& r2, uint32_t& r3,
                                        uint32_t addr) {
    asm volatile("ldmatrix.sync.aligned.m8n8.x4.shared.b16 {%0,%1,%2,%3}, [%4];"
                 : "=r"(r0), "=r"(r1), "=r"(r2), "=r"(r3) : "r"(addr));
}
__device__ __forceinline__ void mma16816(float* c, const uint32_t* a, uint32_t b0, uint32_t b1) {
    asm volatile(
        "mma.sync.aligned.m16n8k16.row.col.f32.bf16.bf16.f32 "
        "{%0,%1,%2,%3}, {%4,%5,%6,%7}, {%8,%9}, {%0,%1,%2,%3};"
        : "+f"(c[0]), "+f"(c[1]), "+f"(c[2]), "+f"(c[3])
        : "r"(a[0]), "r"(a[1]), "r"(a[2]), "r"(a[3]), "r"(b0), "r"(b1));
}
__device__ __forceinline__ float sigf(float x) { return 1.f / (1.f + __expf(-x)); }
#define CP_ASYNC16(dst, src) \
    asm volatile("cp.async.cg.shared.global [%0], [%1], 16;" :: "r"(dst), "l"(src) : "memory")
#define CP_COMMIT() asm volatile("cp.async.commit_group;" ::: "memory")
#define CP_WAIT(n)  asm volatile("cp.async.wait_group %0;" :: "n"(n) : "memory")

// ---------------- packW: 64x64 smem-transpose tiles, coalesced both sides ----------------
__global__ __launch_bounds__(256) void packW_kernel(
    const float* __restrict__ Wif, const float* __restrict__ Wii,
    const float* __restrict__ Wig, const float* __restrict__ Wio)
{
    __shared__ float ts[64][65];
    const int tid = threadIdx.x;
    const int k0 = blockIdx.x * 64, h0 = blockIdx.y * 64, gate = blockIdx.z;
    const float* W = (gate == 0) ? Wif : (gate == 1) ? Wii : (gate == 2) ? Wig : Wio;
#pragma unroll
    for (int q = 0; q < 16; ++q) {
        int i = tid + q * 256;
        int r = i >> 6, c = i & 63;
        ts[r][c] = W[(size_t)(k0 + r) * Hdim + h0 + c];   // coalesced read
    }
    __syncthreads();
#pragma unroll
    for (int q = 0; q < 16; ++q) {
        int i = tid + q * 256;
        int h = i >> 6, kk = i & 63;
        float v = ts[kk][h];
        __nv_bfloat16 hi = __float2bfloat16(v);
        __nv_bfloat16 lo = __float2bfloat16(v - __bfloat162float(hi));
        size_t base = (size_t)(gate * 1024 + h0 + h) * KP + k0 + kk;  // coalesced writes over kk
        g_Wbp[base]        = hi;
        g_Wbp[base + 1024] = hi;
        g_Wbp[base + 2048] = lo;
    }
}
__global__ void bias_kernel(const float* __restrict__ bif_, const float* __restrict__ bhf,
                            const float* __restrict__ bii_, const float* __restrict__ bhi,
                            const float* __restrict__ big_, const float* __restrict__ bhg,
                            const float* __restrict__ bio_, const float* __restrict__ bho)
{
    int idx = blockIdx.x * blockDim.x + threadIdx.x;
    if (idx >= G4) return;
    int gate = idx >> 10, hid = idx & 1023;
    const float* bx = (gate == 0) ? bif_ : (gate == 1) ? bii_ : (gate == 2) ? big_ : bio_;
    const float* bh = (gate == 0) ? bhf  : (gate == 1) ? bhi  : (gate == 2) ? bhg  : bho;
    g_bsum[idx] = bx[hid] + bh[hid];
}

// ---------------- xconv: one block per m-row, 32-bit math, float4 IO ----------------
__global__ __launch_bounds__(256) void xconv_kernel(const float* __restrict__ x)
{
    const int m = blockIdx.x;             // m = t*64 + b
    const int b = m & 63, t = m >> 6;
    const float4* __restrict__ xr = (const float4*)(x + (size_t)(b * Tlen + t) * Idim);
    uint32_t* __restrict__ dst = (uint32_t*)(g_xbf + (size_t)m * KP);
    const int j = threadIdx.x;            // 0..255, 4 elems each
    float4 v = xr[j];
    __nv_bfloat16 h0 = __float2bfloat16(v.x), h1 = __float2bfloat16(v.y);
    __nv_bfloat16 h2 = __float2bfloat16(v.z), h3 = __float2bfloat16(v.w);
    __nv_bfloat16 l0 = __float2bfloat16(v.x - __bfloat162float(h0));
    __nv_bfloat16 l1 = __float2bfloat16(v.y - __bfloat162float(h1));
    __nv_bfloat16 l2 = __float2bfloat16(v.z - __bfloat162float(h2));
    __nv_bfloat16 l3 = __float2bfloat16(v.w - __bfloat162float(h3));
    uint32_t hp0 = (uint32_t)__bfloat16_as_ushort(h0) | ((uint32_t)__bfloat16_as_ushort(h1) << 16);
    uint32_t hp1 = (uint32_t)__bfloat16_as_ushort(h2) | ((uint32_t)__bfloat16_as_ushort(h3) << 16);
    uint32_t lp0 = (uint32_t)__bfloat16_as_ushort(l0) | ((uint32_t)__bfloat16_as_ushort(l1) << 16);
    uint32_t lp1 = (uint32_t)__bfloat16_as_ushort(l2) | ((uint32_t)__bfloat16_as_ushort(l3) << 16);
    dst[j * 2]       = hp0; dst[j * 2 + 1]       = hp1;   // sec0 = hi
    dst[512 + j * 2] = lp0; dst[512 + j * 2 + 1] = lp1;   // sec1 = lo
    dst[1024 + j * 2] = hp0; dst[1024 + j * 2 + 1] = hp1; // sec2 = hi
}

// ---------------- HMMA input projection, cp.async double buffer, 2 CTA/SM ----------------
#define PBK   32
#define PNCH  (KP / PBK)   // 96
#define SROW  40           // 80 B rows

__global__ __launch_bounds__(256, 2) void proj_mma_kernel()
{
    __shared__ __align__(16) __nv_bfloat16 sA[2][128 * SROW];
    __shared__ __align__(16) __nv_bfloat16 sB[2][128 * SROW];

    const int tid = threadIdx.x, lane = tid & 31, wid = tid >> 5;
    const int bn0 = blockIdx.x * 128, bm0 = blockIdx.y * 128;
    const int wm = wid >> 2, wn = wid & 3;

    const uint32_t sAb = smem_to_u32(sA);
    const uint32_t sBb = smem_to_u32(sB);
    const int rowoff = ((lane >> 3) & 1) * 8 + (lane & 7);
    const int kkoff  = (lane >> 4) * 8;
    const int lrow = tid >> 2, lj = tid & 3;   // loader: row 0..63(+64), 16B chunk

    float acc[4][4][4];
#pragma unroll
    for (int i = 0; i < 4; ++i)
#pragma unroll
        for (int j = 0; j < 4; ++j)
#pragma unroll
            for (int r = 0; r < 4; ++r) acc[i][j][r] = 0.f;

    // issue chunk 0
#pragma unroll
    for (int q = 0; q < 2; ++q) {
        int row = lrow + q * 64;
        CP_ASYNC16(sAb + row * 80 + lj * 16, g_xbf + (size_t)(bm0 + row) * KP + lj * 8);
        CP_ASYNC16(sBb + row * 80 + lj * 16, g_Wbp + (size_t)(bn0 + row) * KP + lj * 8);
    }
    CP_COMMIT();

    int buf = 0;
    for (int ch = 0; ch < PNCH; ++ch) {
        if (ch + 1 < PNCH) {
            const int kb = (ch + 1) * PBK;
            const uint32_t da = sAb + (buf ^ 1) * (128 * SROW * 2);
            const uint32_t db = sBb + (buf ^ 1) * (128 * SROW * 2);
#pragma unroll
            for (int q = 0; q < 2; ++q) {
                int row = lrow + q * 64;
                CP_ASYNC16(da + row * 80 + lj * 16, g_xbf + (size_t)(bm0 + row) * KP + kb + lj * 8);
                CP_ASYNC16(db + row * 80 + lj * 16, g_Wbp + (size_t)(bn0 + row) * KP + kb + lj * 8);
            }
            CP_COMMIT();
            CP_WAIT(1);
        } else {
            CP_WAIT(0);
        }
        __syncthreads();
        const uint32_t aBase = sAb + buf * (128 * SROW * 2);
        const uint32_t bBase = sBb + buf * (128 * SROW * 2);
#pragma unroll
        for (int k0 = 0; k0 < PBK; k0 += 16) {
            uint32_t af[4][4], bfr[2][4];
#pragma unroll
            for (int mt = 0; mt < 4; ++mt)
                ldsm_x4(af[mt][0], af[mt][1], af[mt][2], af[mt][3],
                        aBase + (uint32_t)(((wm * 64 + mt * 16 + rowoff) * SROW + k0 + kkoff) * 2));
#pragma unroll
            for (int pt = 0; pt < 2; ++pt)
                ldsm_x4(bfr[pt][0], bfr[pt][1], bfr[pt][2], bfr[pt][3],
                        bBase + (uint32_t)(((wn * 32 + pt * 16 + rowoff) * SROW + k0 + kkoff) * 2));
#pragma unroll
            for (int mt = 0; mt < 4; ++mt)
#pragma unroll
                for (int nt = 0; nt < 4; ++nt) {
                    int pt = nt >> 1, hi = nt & 1;
                    mma16816(acc[mt][nt], af[mt], bfr[pt][hi], bfr[pt][hi + 2]);
                }
        }
        __syncthreads();
        buf ^= 1;
    }

    // epilogue -> xg [cta 256][t][row 64][unit*4+gate], bias folded
    const int erow = lane >> 2, ecol = (lane & 3) * 2;
#pragma unroll
    for (int mt = 0; mt < 4; ++mt)
#pragma unroll
        for (int nt = 0; nt < 4; ++nt) {
            int r = bm0 + wm * 64 + mt * 16 + erow;     // m = t*64 + b
            int c = bn0 + wn * 32 + nt * 8 + ecol;
            int tt = r >> 6, b = r & 63;
            int gate = c >> 10, hid = c & 1023, cta = hid >> 2, u = hid & 3;
            size_t base = (size_t)cta * (512 * 64 * 16) + (size_t)tt * 1024 + b * 16 + u * 4 + gate;
            float b0 = g_bsum[c], b1 = g_bsum[c + 1];
            g_xg[base]           = acc[mt][nt][0] + b0;
            g_xg[base + 4]       = acc[mt][nt][1] + b1;   // unit u+1
            g_xg[base + 128]     = acc[mt][nt][2] + b0;   // row b+8
            g_xg[base + 128 + 4] = acc[mt][nt][3] + b1;
        }
}

// ---------------- grid barrier ----------------
__device__ __forceinline__ void grid_sync(unsigned nb)
{
    __threadfence();
    __syncthreads();
    if (threadIdx.x == 0) {
        unsigned gen = *(volatile unsigned*)&g_bar_gen;
        unsigned arr = atomicAdd(&g_bar_cnt, 1);
        if (arr == nb - 1) {
            g_bar_cnt = 0;
            __threadfence();
            *(volatile unsigned*)&g_bar_gen = gen + 1;
        } else {
            while (*(volatile unsigned*)&g_bar_gen == gen) { __nanosleep(32); }
        }
    }
    __syncthreads();
}

// ---------------- HMMA persistent recurrence: 256 CTAs x 16 cols, 2 CTA/SM ----------------
// CTA owns 4 hidden units x 4 gates; Bs col c = unit*4 + gate (16 cols, K'=3072, pitch 3080).
// Warps: mt = wid&3 (16 rows), kh = wid>>2 (K-half). Cells: thread = (row, unit).
#define BPITCH 3080
#define BS_BYTES (16 * BPITCH * 2)          // 98560
#define RED_OFF  BS_BYTES                   // 4096 B
#define PSM_OFF  (BS_BYTES + 4096)          // 64*20*4 = 5120 B
#define REC_SMEM (BS_BYTES + 4096 + 5120)   // 107776

__global__ __launch_bounds__(256, 2) void lstm_rec_mma(
    const float* __restrict__ Whf, const float* __restrict__ Whi,
    const float* __restrict__ Whg, const float* __restrict__ Who,
    float* __restrict__ out)
{
    extern __shared__ __align__(16) char smr[];
    __nv_bfloat16* Bs = (__nv_bfloat16*)smr;
    float* red = (float*)(smr + RED_OFF);    // [mt 4][row 16][col 16]
    float* psm = (float*)(smr + PSM_OFF);    // [row 64][pitch 20]

    const int tid = threadIdx.x, lane = tid & 31, wid = tid >> 5;
    const int cta = blockIdx.x;              // 0..255
    const int mt = wid & 3, kh = wid >> 2;
    const unsigned NB = gridDim.x;

    // fill Wh' slice (col c = u*4+gate): sec0,1 = hi, sec2 = lo
    for (int idx = tid; idx < 16 * 1024; idx += 256) {
        int c = idx & 15, k = idx >> 4;
        int u = c >> 2, gate = c & 3;
        const float* W = (gate == 0) ? Whf : (gate == 1) ? Whi : (gate == 2) ? Whg : Who;
        float v = W[(size_t)k * Hdim + cta * 4 + u];
        __nv_bfloat16 hi = __float2bfloat16(v);
        __nv_bfloat16 lo = __float2bfloat16(v - __bfloat162float(hi));
        Bs[c * BPITCH + k]        = hi;
        Bs[c * BPITCH + 1024 + k] = hi;
        Bs[c * BPITCH + 2048 + k] = lo;
    }
    // zero h buf0: 65536 u32 over 65536 grid threads
    g_hF[cta * 256 + tid] = 0u;
    grid_sync(NB);

    const uint32_t Bbase = smem_to_u32(Bs);
    const int rowoff = ((lane >> 3) & 1) * 8 + (lane & 7);
    const int kkoff  = (lane >> 4) * 8;
    const int erow   = lane >> 2;
    const int uu     = (lane & 3) * 2;
    // cell identity
    const int crow = tid >> 2, cu = tid & 3;
    const int K    = cta * 4 + cu;           // global hidden unit
    const size_t ctaSlab = (size_t)cta * (512 * 64 * 16);
    // producer fragment address pieces for (crow, K)
    const int pmt = crow >> 4, prr = crow & 15;
    const int c16 = K & 15;
    const int plane = (prr & 7) * 4 + ((c16 >> 1) & 3);
    const int preg  = (prr >> 3) + 2 * (c16 >> 3);
    const int phalf = K & 1;
    const int ktHi = K >> 4, ktLo = 64 + (K >> 4);
    float cst = 0.f;                          // c state

    for (int t = 0; t < Tlen; ++t) {
        const uint32_t* __restrict__ hF = g_hF + (size_t)(t & 1) * 65536;
        // per-cell xg prefetch: float4 = (f,i,g,o)
        float4 xv = *(const float4*)(g_xg + ctaSlab + (size_t)t * 1024 + crow * 16 + cu * 4);

        float acc[2][4];
#pragma unroll
        for (int i = 0; i < 2; ++i)
#pragma unroll
            for (int j = 0; j < 4; ++j) acc[i][j] = 0.f;

        const int ktb = kh * 96;
#pragma unroll 4
        for (int s = 0; s < 96; ++s) {
            const int ktl = ktb + s;
            const int kt  = (ktl < 128) ? ktl : ktl - 128;
            uint4 av4 = *(const uint4*)(hF + ((kt * 4 + mt) * 32 + lane) * 4);
            uint32_t av[4] = {av4.x, av4.y, av4.z, av4.w};
            uint32_t bb[4];
            ldsm_x4(bb[0], bb[1], bb[2], bb[3],
                    Bbase + (uint32_t)((rowoff * BPITCH + ktl * 16 + kkoff) * 2));
            mma16816(acc[0], av, bb[0], bb[2]);   // cols 0-7
            mma16816(acc[1], av, bb[1], bb[3]);   // cols 8-15
        }

        if (kh == 1) {
#pragma unroll
            for (int nt = 0; nt < 2; ++nt) {
                int base = mt * 256 + erow * 16 + nt * 8 + uu;
                *(float2*)&red[base]            = make_float2(acc[nt][0], acc[nt][1]);
                *(float2*)&red[base + 8 * 16]   = make_float2(acc[nt][2], acc[nt][3]);
            }
        }
        __syncthreads();
        if (kh == 0) {
#pragma unroll
            for (int nt = 0; nt < 2; ++nt) {
                int rbase = mt * 256 + erow * 16 + nt * 8 + uu;
                float2 r1 = *(float2*)&red[rbase];
                float2 r2 = *(float2*)&red[rbase + 128];
                int row = mt * 16 + erow;
                *(float2*)&psm[row * 20 + nt * 8 + uu] =
                    make_float2(acc[nt][0] + r1.x, acc[nt][1] + r1.y);
                *(float2*)&psm[(row + 8) * 20 + nt * 8 + uu] =
                    make_float2(acc[nt][2] + r2.x, acc[nt][3] + r2.y);
            }
        }
        __syncthreads();
        // cell phase: all 256 threads, one (row, unit) each
        {
            float4 pm = *(const float4*)&psm[crow * 20 + cu * 4];
            float f  = sigf(pm.x + xv.x);
            float ii = sigf(pm.y + xv.y);
            float gg = tanhf(pm.z + xv.z);
            float oo = sigf(pm.w + xv.w);
            float cn = f * cst + ii * gg;
            cst = cn;
            float hn = tanhf(cn) * oo;
            __nv_bfloat16 hi = __float2bfloat16(hn);
            __nv_bfloat16 lo = __float2bfloat16(hn - __bfloat162float(hi));
            __nv_bfloat16* hw = (__nv_bfloat16*)(g_hF + (size_t)((t + 1) & 1) * 65536);
            hw[(((ktHi * 4 + pmt) * 32 + plane) * 4 + preg) * 2 + phalf] = hi;
            hw[(((ktLo * 4 + pmt) * 32 + plane) * 4 + preg) * 2 + phalf] = lo;
            if (t == Tlen - 1) {
                out[crow * 1024 + K]         = hn;
                out[65536 + crow * 1024 + K] = cn;
            }
        }
        grid_sync(NB);
    }
}

// ---------------- launch ----------------
extern "C" void kernel_launch(void* const* d_in, const int* in_sizes, int n_in,
                              void* d_out, int out_size)
{
    // metadata order = setup_inputs() dict order:
    // 0:x, 1:W_ii, 2:W_hi, 3:W_if, 4:W_hf, 5:W_ig, 6:W_hg, 7:W_io, 8:W_ho,
    // 9:b_ii, 10:b_hi, 11:b_if, 12:b_hf, 13:b_ig, 14:b_hg, 15:b_io, 16:b_ho
    const float* x   = (const float*)d_in[0];
    const float* Wii = (const float*)d_in[1];
    const float* Whi = (const float*)d_in[2];
    const float* Wif = (const float*)d_in[3];
    const float* Whf = (const float*)d_in[4];
    const float* Wig = (const float*)d_in[5];
    const float* Whg = (const float*)d_in[6];
    const float* Wio = (const float*)d_in[7];
    const float* Who = (const float*)d_in[8];
    const float* bii = (const float*)d_in[9];
    const float* bhi = (const float*)d_in[10];
    const float* bif = (const float*)d_in[11];
    const float* bhf = (const float*)d_in[12];
    const float* big = (const float*)d_in[13];
    const float* bhg = (const float*)d_in[14];
    const float* bio = (const float*)d_in[15];
    const float* bho = (const float*)d_in[16];
    float* out = (float*)d_out;

    packW_kernel<<<dim3(16, 16, 4), 256>>>(Wif, Wii, Wig, Wio);
    bias_kernel<<<16, 256>>>(bif, bhf, bii, bhi, big, bhg, bio, bho);
    xconv_kernel<<<Tlen * Bsz, 256>>>(x);
    proj_mma_kernel<<<dim3(G4 / 128, (Tlen * Bsz) / 128), 256>>>();
    cudaFuncSetAttribute(lstm_rec_mma, cudaFuncAttributeMaxDynamicSharedMemorySize, REC_SMEM);
    lstm_rec_mma<<<256, 256, REC_SMEM>>>(Whf, Whi, Whg, Who, out);
}